// round 10
// baseline (speedup 1.0000x reference)
#include <cuda_runtime.h>
#include <cstdint>

#define B_      2048
#define D_      512
#define NA_     512
#define CAP_    32
#define NVMAX_  8
#define WARPS_  8
#define NSL_    2
#define RPW_    32                  // rows per warp: 512 / (8 warps * 2 slices)
#define KC_     16                  // k per chunk (64B per row per chunk)
#define NCH_    32                  // chunks per pass (512/16)
#define SLOT4_  (RPW_ * 4)          // 128 float4 per slot (32 rows x 4 f4)
#define RING4_  (2 * SLOT4_)        // 256 float4 per warp (2 slots)
#define SV4OFF_ (WARPS_ * RING4_)   // 2048
#define SMEMB_  ((SV4OFF_ + NVMAX_ * 128) * 16)   // 49152 B -> 4 CTAs/SM

// ---------------- device scratch ----------------
__device__ int g_counts[NA_];
__device__ int g_buckets[NA_ * CAP_];
__device__ int g_ovf_count;
__device__ int g_ovf[B_];

// ---------------- kernel 1: zero + bucket ----------------
__global__ void k_prep(const int* __restrict__ attrs) {
    int tid = threadIdx.x;                 // 1024 threads, 1 block
    if (tid < NA_) g_counts[tid] = 0;
    if (tid == NA_) g_ovf_count = 0;
    __syncthreads();
    for (int b = tid; b < B_; b += 1024) {
        int a = attrs[b];
        int pos = atomicAdd(&g_counts[a], 1);
        if (pos < CAP_) {
            g_buckets[a * CAP_ + pos] = b;
        } else {
            int o = atomicAdd(&g_ovf_count, 1);
            g_ovf[o] = b;
        }
    }
}

// ---------------- cp.async helpers ----------------
__device__ __forceinline__ void cp16(uint32_t saddr, const void* gaddr) {
    asm volatile("cp.async.cg.shared.global [%0], [%1], 16;"
                 :: "r"(saddr), "l"(gaddr));
}
__device__ __forceinline__ void cp_commit() {
    asm volatile("cp.async.commit_group;");
}
template <int N>
__device__ __forceinline__ void cp_wait() {
    asm volatile("cp.async.wait_group %0;" :: "n"(N));
}

// stage one k-chunk (32 rows x 16 k = 2KB) into a swizzled smem slot.
// lane -> (row = i*8 + lane>>2, off = lane&3); smem addr4 = row*4 + (off^(row&3)).
// Writer phases hit 8 distinct 16B bank-groups (proof: {off^c, 4+(off^c')} perms).
__device__ __forceinline__ void issue_chunk(
    uint32_t sslot, const float4* __restrict__ gbase, int c, int lane)
{
    int sub = lane >> 2;        // 0..7: row-within-group
    int off = lane & 3;         // 0..3: float4-within-chunk-row
    const float4* g = gbase + c * 4 + off;
#pragma unroll
    for (int i = 0; i < 4; i++) {
        int row = i * 8 + sub;
        uint32_t a4 = (uint32_t)(row * 4 + (off ^ (row & 3)));
        cp16(sslot + a4 * 16, g + (size_t)row * 128);
    }
    cp_commit();
}

// reader: m = slot[lane*4 + (k4 ^ (lane&3))] — conflict-free (XOR bijective)
template <int NV>
__device__ __forceinline__ void chunk_fma(
    const float4* __restrict__ sp, const float4* __restrict__ sv4,
    float* __restrict__ acc, int c, int lane)
{
#pragma unroll
    for (int k4 = 0; k4 < 4; k4++) {
        float4 m = sp[lane * 4 + (k4 ^ (lane & 3))];
#pragma unroll
        for (int j = 0; j < NV; j++) {
            float4 v = sv4[j * 128 + c * 4 + k4];     // broadcast, 1 wf
            acc[j] = fmaf(m.x, v.x, acc[j]);
            acc[j] = fmaf(m.y, v.y, acc[j]);
            acc[j] = fmaf(m.z, v.z, acc[j]);
            acc[j] = fmaf(m.w, v.w, acc[j]);
        }
    }
}

// ---------------- per-warp pass: thread = row, vectors broadcast ---------
template <int NV>
__device__ __forceinline__ void run_pass(
    const float4* __restrict__ gbase,     // matrix + grow0*128 (float4)
    float4* __restrict__ slot0, float4* __restrict__ slot1,
    uint32_t s0, uint32_t s1,
    const float4* __restrict__ sv4,
    const int* __restrict__ ssamp,
    int nv, float* __restrict__ out, int grow0, int lane)
{
    float acc[NV];
#pragma unroll
    for (int j = 0; j < NV; j++) acc[j] = 0.0f;

    issue_chunk(s0, gbase, 0, lane);
    issue_chunk(s1, gbase, 1, lane);

#pragma unroll 1
    for (int c = 0; c < NCH_ - 2; c++) {
        cp_wait<1>();
        __syncwarp();                     // staged data visible to all lanes
        chunk_fma<NV>((c & 1) ? slot1 : slot0, sv4, acc, c, lane);
        __syncwarp();                     // all lanes done reading the slot
        issue_chunk((c & 1) ? s1 : s0, gbase, c + 2, lane);
    }
    {   // c = 30 (slot 0)
        cp_wait<1>();
        __syncwarp();
        chunk_fma<NV>(slot0, sv4, acc, NCH_ - 2, lane);
    }
    {   // c = 31 (slot 1)
        cp_wait<0>();
        __syncwarp();
        chunk_fma<NV>(slot1, sv4, acc, NCH_ - 1, lane);
    }

    int row = grow0 + lane;
#pragma unroll
    for (int j = 0; j < NV; j++)
        if (j < nv)
            out[(size_t)ssamp[j] * D_ + row] = fmaxf(acc[j], 0.0f);
}

// ---------------- kernel 2: per-attribute matvec ------------------------
// grid = (NA_, NSL_), 256 threads (8 warps). Warp owns 32 contiguous rows.
__global__ __launch_bounds__(256, 4) void k_compute(
    const int*   __restrict__ attrs,
    const int*   __restrict__ objs,
    const float* __restrict__ attr_ops,
    const float* __restrict__ obj_emb,
    float*       __restrict__ out)
{
    extern __shared__ float4 smem4[];
    float4* ring = smem4;                          // [8][2][128] f4 = 32 KB
    float4* sv4  = smem4 + SV4OFF_;                // [8][128]    f4 = 16 KB
    __shared__ int ssamp[NVMAX_];

    int tid  = threadIdx.x;
    int lane = tid & 31;
    int warp = tid >> 5;
    int a    = blockIdx.x;

    int cnt = g_counts[a];
    if (cnt > CAP_) cnt = CAP_;

    int grow0 = blockIdx.y * (WARPS_ * RPW_) + warp * RPW_;
    const float4* Mw =
        (const float4*)(attr_ops + (size_t)a * D_ * D_) + (size_t)grow0 * 128;

    float4*  slot0 = ring + warp * RING4_;
    float4*  slot1 = slot0 + SLOT4_;
    uint32_t s0 = (uint32_t)__cvta_generic_to_shared(slot0);
    uint32_t s1 = (uint32_t)__cvta_generic_to_shared(slot1);

    for (int base = 0; base < cnt; base += NVMAX_) {
        int nv = cnt - base;
        if (nv > NVMAX_) nv = NVMAX_;
        int NVsel = (nv <= 1) ? 1 : (nv <= 2) ? 2 : (nv <= 4) ? 4 : 8;

        __syncthreads();                   // prior pass done reading sv4
        if (tid < nv) ssamp[tid] = g_buckets[a * CAP_ + base + tid];
        __syncthreads();

        for (int u = tid; u < NVsel * 128; u += 256) {
            int j = u >> 7;
            float4 val = make_float4(0.f, 0.f, 0.f, 0.f);
            if (j < nv)
                val = ((const float4*)(obj_emb + (size_t)objs[ssamp[j]] * D_))[u & 127];
            sv4[u] = val;
        }
        __syncthreads();

        switch (NVsel) {
            case 1: run_pass<1>(Mw, slot0, slot1, s0, s1, sv4, ssamp, nv, out, grow0, lane); break;
            case 2: run_pass<2>(Mw, slot0, slot1, s0, s1, sv4, ssamp, nv, out, grow0, lane); break;
            case 4: run_pass<4>(Mw, slot0, slot1, s0, s1, sv4, ssamp, nv, out, grow0, lane); break;
            default: run_pass<8>(Mw, slot0, slot1, s0, s1, sv4, ssamp, nv, out, grow0, lane); break;
        }
    }

    // ---- overflow tail (rare; correctness safety net) ----
    int novf = g_ovf_count;
    for (int i = blockIdx.x; i < novf; i += NA_) {
        __syncthreads();
        if (tid == 0) ssamp[0] = g_ovf[i];
        __syncthreads();
        int b = ssamp[0];
        for (int u = tid; u < 128; u += 256)
            sv4[u] = ((const float4*)(obj_emb + (size_t)objs[b] * D_))[u];
        __syncthreads();
        const float4* M2 =
            (const float4*)(attr_ops + (size_t)attrs[b] * D_ * D_) + (size_t)grow0 * 128;
        run_pass<1>(M2, slot0, slot1, s0, s1, sv4, ssamp, 1, out, grow0, lane);
    }
}

// ---------------- launch -------------------------------------------------
extern "C" void kernel_launch(void* const* d_in, const int* in_sizes, int n_in,
                              void* d_out, int out_size)
{
    const int*   attrs    = (const int*)d_in[0];
    const int*   objs     = (const int*)d_in[1];
    const float* attr_ops = (const float*)d_in[2];
    const float* obj_emb  = (const float*)d_in[3];
    float*       out      = (float*)d_out;

    cudaFuncSetAttribute(k_compute,
                         cudaFuncAttributeMaxDynamicSharedMemorySize, SMEMB_);

    k_prep<<<1, 1024>>>(attrs);
    k_compute<<<dim3(NA_, NSL_), 256, SMEMB_>>>(attrs, objs, attr_ops, obj_emb, out);
}

// round 11
// speedup vs baseline: 1.0490x; 1.0490x over previous
#include <cuda_runtime.h>
#include <cstdint>

#define B_      2048
#define D_      512
#define NA_     512
#define CAP_    32
#define NVMAX_  8
#define WARPS_  8
#define NSL_    2
#define RPW_    32                  // rows per warp: 512 / (8 warps * 2 slices)
#define KC_     16                  // k per chunk (64B per row per chunk)
#define NCH_    32                  // chunks per pass (512/16)
#define DEPTH_  3
#define SLOT4_  (RPW_ * 4)          // 128 float4 per slot (32 rows x 4 f4 = 2KB)
#define RING4_  (DEPTH_ * SLOT4_)   // 384 float4 per warp
#define SV4OFF_ (WARPS_ * RING4_)   // 3072
#define SMEMB_  ((SV4OFF_ + NVMAX_ * 128) * 16)   // 65536 B -> 3 CTAs/SM

// ---------------- device scratch (zero-initialized at load; consumer-zeroed
// after every use so each graph replay sees clean state) ----------------
__device__ int g_counts[NSL_][NA_];
__device__ int g_buckets[NA_ * CAP_];

// ---------------- kernel 1: bucket by attribute (no zero phase) ----------
__global__ void k_bucket(const int* __restrict__ attrs) {
    int b = blockIdx.x * blockDim.x + threadIdx.x;
    if (b >= B_) return;
    int a = attrs[b];
    int pos = atomicAdd(&g_counts[0][a], 1);
    atomicAdd(&g_counts[1][a], 1);
    if (pos < CAP_) g_buckets[a * CAP_ + pos] = b;
}

// ---------------- cp.async helpers ----------------
__device__ __forceinline__ void cp16(uint32_t saddr, const void* gaddr) {
    asm volatile("cp.async.cg.shared.global [%0], [%1], 16;"
                 :: "r"(saddr), "l"(gaddr));
}
__device__ __forceinline__ void cp_commit() {
    asm volatile("cp.async.commit_group;");
}
template <int N>
__device__ __forceinline__ void cp_wait() {
    asm volatile("cp.async.wait_group %0;" :: "n"(N));
}

// stage one k-chunk (32 rows x 16 k = 2KB) into a swizzled smem slot.
__device__ __forceinline__ void issue_chunk(
    uint32_t sslot, const float4* __restrict__ gbase, int c, int lane)
{
    int sub = lane >> 2;        // 0..7 row-within-group
    int off = lane & 3;         // 0..3 float4-within-chunk-row
    const float4* g = gbase + c * 4 + off;
#pragma unroll
    for (int i = 0; i < 4; i++) {
        int row = i * 8 + sub;
        uint32_t a4 = (uint32_t)(row * 4 + (off ^ (row & 3)));
        cp16(sslot + a4 * 16, g + (size_t)row * 128);
    }
    cp_commit();
}

// reader: slot[lane*4 + (k4 ^ (lane&3))] — XOR bijective, conflict-free
template <int NV>
__device__ __forceinline__ void chunk_fma(
    const float4* __restrict__ sp, const float4* __restrict__ sv4,
    float* __restrict__ acc, int c, int lane)
{
#pragma unroll
    for (int k4 = 0; k4 < 4; k4++) {
        float4 m = sp[lane * 4 + (k4 ^ (lane & 3))];
#pragma unroll
        for (int j = 0; j < NV; j++) {
            float4 v = sv4[j * 128 + c * 4 + k4];     // broadcast, 1 wf
            acc[j] = fmaf(m.x, v.x, acc[j]);
            acc[j] = fmaf(m.y, v.y, acc[j]);
            acc[j] = fmaf(m.z, v.z, acc[j]);
            acc[j] = fmaf(m.w, v.w, acc[j]);
        }
    }
}

// ---------------- per-warp pass: depth-3 cp.async ring --------------------
// Steady state: while computing chunk c, chunks c+1 and c+2 are in flight
// (4KB/warp outstanding) — 2x the depth-2 effective MLP.
template <int NV>
__device__ __forceinline__ void run_pass(
    const float4* __restrict__ gbase,
    float4* __restrict__ ringw, uint32_t ring_s,
    const float4* __restrict__ sv4,
    const int* __restrict__ ssamp,
    int nv, float* __restrict__ out, int grow0, int lane)
{
    float acc[NV];
#pragma unroll
    for (int j = 0; j < NV; j++) acc[j] = 0.0f;

    issue_chunk(ring_s,            gbase, 0, lane);
    issue_chunk(ring_s + 2048,     gbase, 1, lane);
    issue_chunk(ring_s + 4096,     gbase, 2, lane);

    int slot = 0;
#pragma unroll 1
    for (int c = 0; c < NCH_ - 3; c++) {
        cp_wait<2>();
        __syncwarp();
        chunk_fma<NV>(ringw + slot * SLOT4_, sv4, acc, c, lane);
        __syncwarp();
        issue_chunk(ring_s + (uint32_t)slot * 2048, gbase, c + 3, lane);
        slot = (slot == 2) ? 0 : slot + 1;
    }
    // tail: chunks 29(slot 2), 30(slot 0), 31(slot 1)
    cp_wait<2>(); __syncwarp();
    chunk_fma<NV>(ringw + 2 * SLOT4_, sv4, acc, NCH_ - 3, lane);
    cp_wait<1>(); __syncwarp();
    chunk_fma<NV>(ringw,              sv4, acc, NCH_ - 2, lane);
    cp_wait<0>(); __syncwarp();
    chunk_fma<NV>(ringw + 1 * SLOT4_, sv4, acc, NCH_ - 1, lane);

    int row = grow0 + lane;
#pragma unroll
    for (int j = 0; j < NV; j++)
        if (j < nv)
            out[(size_t)ssamp[j] * D_ + row] = fmaxf(acc[j], 0.0f);
}

// ---------------- kernel 2: per-attribute matvec ------------------------
__global__ __launch_bounds__(256) void k_compute(
    const int*   __restrict__ attrs,
    const int*   __restrict__ objs,
    const float* __restrict__ attr_ops,
    const float* __restrict__ obj_emb,
    float*       __restrict__ out)
{
    extern __shared__ float4 smem4[];
    float4* ring = smem4;                          // [8][3][128] f4 = 48 KB
    float4* sv4  = smem4 + SV4OFF_;                // [8][128]    f4 = 16 KB
    __shared__ int ssamp[NVMAX_];

    int tid  = threadIdx.x;
    int lane = tid & 31;
    int warp = tid >> 5;
    int a    = blockIdx.x;
    int y    = blockIdx.y;

    int cnt = g_counts[y][a];

    int grow0 = y * (WARPS_ * RPW_) + warp * RPW_;
    const float4* Mw =
        (const float4*)(attr_ops + (size_t)a * D_ * D_) + (size_t)grow0 * 128;
    float4*  ringw  = ring + warp * RING4_;
    uint32_t ring_s = (uint32_t)__cvta_generic_to_shared(ringw);

    if (cnt <= CAP_) {
        for (int base = 0; base < cnt; base += NVMAX_) {
            int nv = cnt - base;
            if (nv > NVMAX_) nv = NVMAX_;
            int NVsel = (nv <= 1) ? 1 : (nv <= 2) ? 2 : (nv <= 4) ? 4 : 8;

            __syncthreads();                  // prior pass done reading sv4
            if (tid < nv) ssamp[tid] = g_buckets[a * CAP_ + base + tid];
            __syncthreads();

            for (int u = tid; u < NVsel * 128; u += 256) {
                int j = u >> 7;
                float4 val = make_float4(0.f, 0.f, 0.f, 0.f);
                if (j < nv)
                    val = ((const float4*)(obj_emb + (size_t)objs[ssamp[j]] * D_))[u & 127];
                sv4[u] = val;
            }
            __syncthreads();

            switch (NVsel) {
                case 1: run_pass<1>(Mw, ringw, ring_s, sv4, ssamp, nv, out, grow0, lane); break;
                case 2: run_pass<2>(Mw, ringw, ring_s, sv4, ssamp, nv, out, grow0, lane); break;
                case 4: run_pass<4>(Mw, ringw, ring_s, sv4, ssamp, nv, out, grow0, lane); break;
                default: run_pass<8>(Mw, ringw, ring_s, sv4, ssamp, nv, out, grow0, lane); break;
            }
        }
    } else {
        // overflow (cnt > CAP): uniform scan of attrs — correctness safety
        // net for adversarial inputs; never taken for Poisson(4) buckets.
        int nb = 0;
        for (int b = 0; b < B_; b++) {
            if (attrs[b] == a) {
                __syncthreads();
                if (tid == 0) ssamp[nb] = b;
                nb++;
                if (nb == NVMAX_) {
                    __syncthreads();
                    for (int u = tid; u < NVMAX_ * 128; u += 256) {
                        int j = u >> 7;
                        sv4[u] = ((const float4*)(obj_emb +
                                   (size_t)objs[ssamp[j]] * D_))[u & 127];
                    }
                    __syncthreads();
                    run_pass<8>(Mw, ringw, ring_s, sv4, ssamp, NVMAX_, out, grow0, lane);
                    nb = 0;
                }
            }
        }
        if (nb > 0) {
            __syncthreads();
            for (int u = tid; u < NVMAX_ * 128; u += 256) {
                int j = u >> 7;
                float4 val = make_float4(0.f, 0.f, 0.f, 0.f);
                if (j < nb)
                    val = ((const float4*)(obj_emb + (size_t)objs[ssamp[j]] * D_))[u & 127];
                sv4[u] = val;
            }
            __syncthreads();
            run_pass<8>(Mw, ringw, ring_s, sv4, ssamp, nb, out, grow0, lane);
        }
    }

    // restore clean state for next replay (this CTA is the sole reader)
    if (tid == 0) g_counts[y][a] = 0;
}

// ---------------- launch -------------------------------------------------
extern "C" void kernel_launch(void* const* d_in, const int* in_sizes, int n_in,
                              void* d_out, int out_size)
{
    const int*   attrs    = (const int*)d_in[0];
    const int*   objs     = (const int*)d_in[1];
    const float* attr_ops = (const float*)d_in[2];
    const float* obj_emb  = (const float*)d_in[3];
    float*       out      = (float*)d_out;

    cudaFuncSetAttribute(k_compute,
                         cudaFuncAttributeMaxDynamicSharedMemorySize, SMEMB_);

    k_bucket<<<(B_ + 255) / 256, 256>>>(attrs);
    k_compute<<<dim3(NA_, NSL_), 256, SMEMB_>>>(attrs, objs, attr_ops, obj_emb, out);
}